// round 14
// baseline (speedup 1.0000x reference)
#include <cuda_runtime.h>
#include <cuda_bf16.h>
#include <cstdint>
#include <math.h>

// ---------------- problem constants ----------------
#define BATCH 32
#define HH 56
#define WW 56
#define CDIM 384
#define NHEADS 12
#define HDIM 32
#define WSZ 7
#define NTOK 49
#define NWIN 64
#define BN_WIN 2048
#define ROWS 100352
#define HID 1536
#define QKVN 1152

// ---------------- scratch ----------------
__device__ float g_win[(size_t)ROWS * CDIM];
__device__ float g_qkv[(size_t)ROWS * QKVN];
__device__ float g_att[(size_t)ROWS * CDIM];
__device__ float g_hid[(size_t)ROWS * HID];
__device__ float g_qkvT[(size_t)QKVN * CDIM];
__device__ float g_projT[(size_t)CDIM * CDIM];
__device__ float g_fc1T[(size_t)HID * CDIM];
__device__ float g_fc2T[(size_t)CDIM * HID];

// ---------------- helpers ----------------
__device__ __forceinline__ uint32_t s2u(const void* p) {
    uint32_t a;
    asm("{ .reg .u64 t; cvta.to.shared.u64 t, %1; cvt.u32.u64 %0, t; }" : "=r"(a) : "l"(p));
    return a;
}
__device__ __forceinline__ void mma_tf32(float* c, const uint32_t* a, const uint32_t* b) {
    asm volatile(
        "mma.sync.aligned.m16n8k8.row.col.f32.tf32.tf32.f32 "
        "{%0,%1,%2,%3}, {%4,%5,%6,%7}, {%8,%9}, {%0,%1,%2,%3};"
        : "+f"(c[0]), "+f"(c[1]), "+f"(c[2]), "+f"(c[3])
        : "r"(a[0]), "r"(a[1]), "r"(a[2]), "r"(a[3]), "r"(b[0]), "r"(b[1]));
}
__device__ __forceinline__ void ldsm4(uint32_t* r, uint32_t addr) {
    asm volatile("ldmatrix.sync.aligned.m8n8.x4.shared.b16 {%0,%1,%2,%3}, [%4];"
                 : "=r"(r[0]), "=r"(r[1]), "=r"(r[2]), "=r"(r[3]) : "r"(addr));
}
__device__ __forceinline__ void cp16(uint32_t dst, const void* src) {
    asm volatile("cp.async.cg.shared.global [%0], [%1], 16;" :: "r"(dst), "l"(src));
}
#define CP_COMMIT() asm volatile("cp.async.commit_group;" ::: "memory")
#define CP_WAIT0()  asm volatile("cp.async.wait_group 0;" ::: "memory")

// packed f32x2 helpers (PTX sm_100+, not arch-'a' gated)
__device__ __forceinline__ unsigned long long pk2(float lo, float hi) {
    unsigned long long r;
    asm("mov.b64 %0, {%1, %2};" : "=l"(r) : "f"(lo), "f"(hi));
    return r;
}
__device__ __forceinline__ void upk2(float& lo, float& hi, unsigned long long v) {
    asm("mov.b64 {%0, %1}, %2;" : "=f"(lo), "=f"(hi) : "l"(v));
}
__device__ __forceinline__ void ffma2(unsigned long long& d, unsigned long long a,
                                      unsigned long long b) {
    asm("fma.rn.f32x2 %0, %1, %2, %0;" : "+l"(d) : "l"(a), "l"(b));
}

// Branchless erf-based GELU (A&S 7.1.26, abs err <= 1.5e-7)
__device__ __forceinline__ float fast_gelu(float x) {
    float u = x * 0.70710678118654752f;
    float a = fabsf(u);
    float t = __fdividef(1.0f, fmaf(0.3275911f, a, 1.0f));
    float p = fmaf(1.061405429f, t, -1.453152027f);
    p = fmaf(p, t, 1.421413741f);
    p = fmaf(p, t, -0.284496736f);
    p = fmaf(p, t, 0.254829592f);
    p = p * t;
    float e = __expf(-a * a);
    float er = fmaf(-p, e, 1.0f);
    er = copysignf(er, x);
    return 0.5f * x * (1.0f + er);
}

// ======================= tf32 mma.sync GEMM =======================
// Block 128 x (32*NFRAG), 8 warps (2m x 4n), warp tile 64 x (8*NFRAG), BK=32,
// 2-stage cp.async, single __syncthreads per K-chunk.
// EPI: 0 bias+store | 1 bias+scatter+residual | 2 bias+GELU | 3 bias+accumulate
template <int EPI, int NFRAG>
__global__ void __launch_bounds__(256)
mma_gemm(const float* __restrict__ A, const float* __restrict__ Bt,
         const float* __restrict__ bias, float* __restrict__ C,
         int K, int Nm, const float* __restrict__ resid) {
    constexpr int BN = NFRAG * 32;
    constexpr int STAGE = 16384 + BN * 128;
    extern __shared__ __align__(1024) char smem[];
    const uint32_t sb = s2u(smem);

    const int tid = threadIdx.x;
    const int lane = tid & 31, wid = tid >> 5;
    const int wm = wid & 1, wn = wid >> 1;
    const int row0 = blockIdx.y * 128, col0 = blockIdx.x * BN;

    const float* Ab = A + (size_t)row0 * K;
    const float* Bb = Bt + (size_t)col0 * K;

    const int lr = tid >> 3;
    const int lc = tid & 7;

    const int x7 = lane & 7;
    const int rowA = wm * 64 + ((lane >> 3) & 1) * 8 + x7;
    const int cA = lane >> 4;
    const int rowB = wn * (NFRAG * 8) + (lane >> 4) * 8 + x7;
    const int cB = (lane >> 3) & 1;

    float acc[4][NFRAG][4];
#pragma unroll
    for (int i = 0; i < 4; i++)
#pragma unroll
        for (int j = 0; j < NFRAG; j++)
#pragma unroll
            for (int e = 0; e < 4; e++) acc[i][j][e] = 0.0f;

    const int nk = K >> 5;

    auto load_tile = [&](int s, int k0) {
        uint32_t As = sb + s * STAGE;
        uint32_t Bs = As + 16384;
#pragma unroll
        for (int i = 0; i < 4; i++) {
            int r = lr + i * 32;
            uint32_t off = (uint32_t)r * 128 + ((uint32_t)(lc ^ (r & 7)) << 4);
            cp16(As + off, Ab + (size_t)r * K + k0 + lc * 4);
        }
#pragma unroll
        for (int i = 0; i < NFRAG; i++) {
            int r = lr + i * 32;
            uint32_t off = (uint32_t)r * 128 + ((uint32_t)(lc ^ (r & 7)) << 4);
            cp16(Bs + off, Bb + (size_t)r * K + k0 + lc * 4);
        }
    };

    load_tile(0, 0); CP_COMMIT();

    for (int it = 0; it < nk; ++it) {
        CP_WAIT0();
        __syncthreads();                 // all warps past compute(it-1)
        if (it + 1 < nk) load_tile((it + 1) & 1, (it + 1) << 5);
        CP_COMMIT();

        const uint32_t As = sb + (it & 1) * STAGE;
        const uint32_t Bs = As + 16384;
#pragma unroll
        for (int kkp = 0; kkp < 4; kkp++) {
            uint32_t a[4][4], b[NFRAG / 2][4];
#pragma unroll
            for (int mf = 0; mf < 4; mf++) {
                uint32_t addr = As + ((uint32_t)(rowA + mf * 16) << 7) +
                                ((uint32_t)((2 * kkp + cA) ^ x7) << 4);
                ldsm4(a[mf], addr);
            }
#pragma unroll
            for (int pr = 0; pr < NFRAG / 2; pr++) {
                uint32_t addr = Bs + ((uint32_t)(rowB + pr * 16) << 7) +
                                ((uint32_t)((2 * kkp + cB) ^ x7) << 4);
                ldsm4(b[pr], addr);
            }
#pragma unroll
            for (int mf = 0; mf < 4; mf++)
#pragma unroll
                for (int nf = 0; nf < NFRAG; nf++)
                    mma_tf32(acc[mf][nf], a[mf], &b[nf >> 1][(nf & 1) * 2]);
        }
    }

    // ---------------- epilogue ----------------
#pragma unroll
    for (int mf = 0; mf < 4; mf++) {
#pragma unroll
        for (int h = 0; h < 2; h++) {
            int row = row0 + wm * 64 + mf * 16 + (lane >> 2) + h * 8;
            size_t base;
            if (EPI == 1) {
                int bn = row / NTOK, tok = row - bn * NTOK;
                int bbat = bn >> 6, w = bn & 63;
                int ii = (w >> 3) * WSZ + tok / WSZ;
                int jj = (w & 7) * WSZ + tok % WSZ;
                int hh = (ii < 53) ? ii + 3 : ii - 53;
                int ww2 = (jj < 53) ? jj + 3 : jj - 53;
                base = ((size_t)bbat * (HH * WW) + hh * WW + ww2) * CDIM;
            } else {
                base = (size_t)row * Nm;
            }
#pragma unroll
            for (int nf = 0; nf < NFRAG; nf++) {
                int col = col0 + wn * (NFRAG * 8) + nf * 8 + (lane & 3) * 2;
                float v0 = acc[mf][nf][h * 2 + 0] + bias[col];
                float v1 = acc[mf][nf][h * 2 + 1] + bias[col + 1];
                if (EPI == 2) {
                    v0 = fast_gelu(v0);
                    v1 = fast_gelu(v1);
                }
                size_t off = base + col;
                if (EPI == 1) {
                    float2 rr = *(const float2*)(resid + off);
                    float2 o; o.x = v0 + rr.x; o.y = v1 + rr.y;
                    *(float2*)(C + off) = o;
                } else if (EPI == 3) {
                    float2 o = *(float2*)(C + off);
                    o.x += v0; o.y += v1;
                    *(float2*)(C + off) = o;
                } else {
                    float2 o; o.x = v0; o.y = v1;
                    *(float2*)(C + off) = o;
                }
            }
        }
    }
}

#define GSMEM_6 (2 * (16384 + 192 * 128))   // 81920
#define GSMEM_8 (2 * (16384 + 256 * 128))   // 98304

// ---------------- weight transpose [K,N] -> [N,K] ----------------
__global__ void transpose_k(const float* __restrict__ W, float* __restrict__ Wt,
                            int K, int N) {
    __shared__ float t[32][33];
    int k0 = blockIdx.y * 32, n0 = blockIdx.x * 32;
    int x = threadIdx.x, y = threadIdx.y;
    for (int i = y; i < 32; i += 8) t[i][x] = W[(size_t)(k0 + i) * N + n0 + x];
    __syncthreads();
    for (int i = y; i < 32; i += 8) Wt[(size_t)(n0 + i) * K + k0 + x] = t[x][i];
}

// ---------------- LN1 + cyclic shift + window partition ----------------
__global__ void ln1_part_kernel(const float* __restrict__ x,
                                const float* __restrict__ g,
                                const float* __restrict__ b,
                                float* __restrict__ out) {
    int row = blockIdx.x;
    int tid = threadIdx.x;
    const float* xr = x + (size_t)row * CDIM;
    float v0 = xr[tid], v1 = xr[tid + 128], v2 = xr[tid + 256];
    float s = v0 + v1 + v2;
    float sq = v0 * v0 + v1 * v1 + v2 * v2;
#pragma unroll
    for (int o = 16; o; o >>= 1) {
        s += __shfl_down_sync(0xffffffffu, s, o);
        sq += __shfl_down_sync(0xffffffffu, sq, o);
    }
    __shared__ float rs[4], rq[4];
    int w = tid >> 5, l = tid & 31;
    if (l == 0) { rs[w] = s; rq[w] = sq; }
    __syncthreads();
    float ts = rs[0] + rs[1] + rs[2] + rs[3];
    float tq = rq[0] + rq[1] + rq[2] + rq[3];
    float mean = ts * (1.0f / CDIM);
    float var = tq * (1.0f / CDIM) - mean * mean;
    float rstd = rsqrtf(var + 1e-5f);

    int bb = row / (HH * WW);
    int rem = row - bb * (HH * WW);
    int hh = rem / WW, ww = rem - (rem / WW) * WW;
    int i = (hh >= 3) ? hh - 3 : hh + 53;
    int j = (ww >= 3) ? ww - 3 : ww + 53;
    int widx = (i / WSZ) * 8 + (j / WSZ);
    int tok = (i % WSZ) * WSZ + (j % WSZ);
    size_t drow = ((size_t)(bb * NWIN + widx) * NTOK + tok) * CDIM;
    out[drow + tid]       = (v0 - mean) * rstd * g[tid]       + b[tid];
    out[drow + tid + 128] = (v1 - mean) * rstd * g[tid + 128] + b[tid + 128];
    out[drow + tid + 256] = (v2 - mean) * rstd * g[tid + 256] + b[tid + 256];
}

// ---------------- LN2 ----------------
__global__ void ln2_kernel(const float* __restrict__ x,
                           const float* __restrict__ g,
                           const float* __restrict__ b,
                           float* __restrict__ out) {
    int row = blockIdx.x;
    int tid = threadIdx.x;
    const float* xr = x + (size_t)row * CDIM;
    float v0 = xr[tid], v1 = xr[tid + 128], v2 = xr[tid + 256];
    float s = v0 + v1 + v2;
    float sq = v0 * v0 + v1 * v1 + v2 * v2;
#pragma unroll
    for (int o = 16; o; o >>= 1) {
        s += __shfl_down_sync(0xffffffffu, s, o);
        sq += __shfl_down_sync(0xffffffffu, sq, o);
    }
    __shared__ float rs[4], rq[4];
    int w = tid >> 5, l = tid & 31;
    if (l == 0) { rs[w] = s; rq[w] = sq; }
    __syncthreads();
    float ts = rs[0] + rs[1] + rs[2] + rs[3];
    float tq = rq[0] + rq[1] + rq[2] + rq[3];
    float mean = ts * (1.0f / CDIM);
    float var = tq * (1.0f / CDIM) - mean * mean;
    float rstd = rsqrtf(var + 1e-5f);
    size_t o0 = (size_t)row * CDIM;
    out[o0 + tid]       = (v0 - mean) * rstd * g[tid]       + b[tid];
    out[o0 + tid + 128] = (v1 - mean) * rstd * g[tid + 128] + b[tid + 128];
    out[o0 + tid + 256] = (v2 - mean) * rstd * g[tid + 256] + b[tid + 256];
}

// ---------------- attention v2: row-per-thread, scores in registers ----------------
// Block = (window, head), 64 threads. Thread i owns output row i (i < 49).
// K/V staged in smem, read as broadcast LDS.128. q/scores/softmax fully in regs.
// Packed fma.rn.f32x2 halves FMA issue count.
__global__ __launch_bounds__(64)
void attn_kernel(const float* __restrict__ qkv, const float* __restrict__ rpb,
                 const float* __restrict__ mask, float* __restrict__ out) {
    int bn = blockIdx.x;
    int h = blockIdx.y;
    int tid = threadIdx.x;

    __shared__ __align__(16) float ks[NTOK][HDIM];
    __shared__ __align__(16) float vs[NTOK][HDIM];

    const float* qbase = qkv + (size_t)bn * NTOK * QKVN + h * HDIM;
    // cooperative K/V load: 49 rows x 8 float4
    for (int t = tid; t < NTOK * 8; t += 64) {
        int r = t >> 3, c = t & 7;
        const float4* src = (const float4*)(qbase + (size_t)r * QKVN);
        *(float4*)&ks[r][c * 4] = src[96 + c];         // +CDIM  (384 floats = 96 float4)
        *(float4*)&vs[r][c * 4] = src[192 + c];        // +2*CDIM
    }

    bool valid = tid < NTOK;
    unsigned long long qp[16];
    if (valid) {
        const float4* qr = (const float4*)(qbase + (size_t)tid * QKVN);
#pragma unroll
        for (int c = 0; c < 8; c++) {
            float4 v = qr[c];
            float sc = 0.17677669529663687f;
            qp[2 * c + 0] = pk2(v.x * sc, v.y * sc);
            qp[2 * c + 1] = pk2(v.z * sc, v.w * sc);
        }
    }
    __syncthreads();

    float s[NTOK];
    if (valid) {
        const float* mrow = mask + (size_t)(bn & 63) * (NTOK * NTOK) + tid * NTOK;
        int yi = tid / WSZ, xi = tid - yi * WSZ;
#pragma unroll 7
        for (int j = 0; j < NTOK; j++) {
            int yj = j / WSZ, xj = j - yj * WSZ;
            float base = rpb[((yi - yj + 6) * 13 + (xi - xj + 6)) * NHEADS + h] + mrow[j];
            unsigned long long a0 = 0, a1 = 0;
            const ulonglong2* kr = (const ulonglong2*)&ks[j][0];
#pragma unroll
            for (int c = 0; c < 8; c++) {
                ulonglong2 kk = kr[c];
                ffma2(a0, kk.x, qp[2 * c + 0]);
                ffma2(a1, kk.y, qp[2 * c + 1]);
            }
            float l0, h0, l1, h1;
            upk2(l0, h0, a0);
            upk2(l1, h1, a1);
            s[j] = base + ((l0 + h0) + (l1 + h1));
        }
        // softmax (thread-local)
        float m = -1e30f;
#pragma unroll
        for (int j = 0; j < NTOK; j++) m = fmaxf(m, s[j]);
        float sum = 0.0f;
#pragma unroll
        for (int j = 0; j < NTOK; j++) {
            float e = __expf(s[j] - m);
            s[j] = e;
            sum += e;
        }
        float inv = __fdividef(1.0f, sum);

        unsigned long long o[16];
#pragma unroll
        for (int k = 0; k < 16; k++) o[k] = 0;
#pragma unroll 7
        for (int j = 0; j < NTOK; j++) {
            float w = s[j] * inv;
            unsigned long long wp = pk2(w, w);
            const ulonglong2* vr = (const ulonglong2*)&vs[j][0];
#pragma unroll
            for (int c = 0; c < 8; c++) {
                ulonglong2 vv = vr[c];
                ffma2(o[2 * c + 0], vv.x, wp);
                ffma2(o[2 * c + 1], vv.y, wp);
            }
        }
        float ov[32];
#pragma unroll
        for (int k = 0; k < 16; k++) upk2(ov[2 * k], ov[2 * k + 1], o[k]);
        float* dst = out + ((size_t)bn * NTOK + tid) * CDIM + h * HDIM;
#pragma unroll
        for (int c = 0; c < 8; c++)
            *(float4*)(dst + c * 4) = make_float4(ov[4 * c], ov[4 * c + 1],
                                                  ov[4 * c + 2], ov[4 * c + 3]);
    }
}

// ---------------- launch ----------------
extern "C" void kernel_launch(void* const* d_in, const int* in_sizes, int n_in,
                              void* d_out, int out_size) {
    const float* x        = (const float*)d_in[0];
    const float* attnmask = (const float*)d_in[1];
    const float* n1g      = (const float*)d_in[2];
    const float* n1b      = (const float*)d_in[3];
    const float* qkv_w    = (const float*)d_in[4];
    const float* qkv_b    = (const float*)d_in[5];
    const float* rpb      = (const float*)d_in[6];
    const float* proj_w   = (const float*)d_in[7];
    const float* proj_b   = (const float*)d_in[8];
    const float* n2g      = (const float*)d_in[9];
    const float* n2b      = (const float*)d_in[10];
    const float* fc1_w    = (const float*)d_in[11];
    const float* fc1_b    = (const float*)d_in[12];
    const float* fc2_w    = (const float*)d_in[13];
    const float* fc2_b    = (const float*)d_in[14];
    float* out = (float*)d_out;

    float *p_win, *p_qkv, *p_att, *p_hid, *p_qkvT, *p_projT, *p_fc1T, *p_fc2T;
    cudaGetSymbolAddress((void**)&p_win, g_win);
    cudaGetSymbolAddress((void**)&p_qkv, g_qkv);
    cudaGetSymbolAddress((void**)&p_att, g_att);
    cudaGetSymbolAddress((void**)&p_hid, g_hid);
    cudaGetSymbolAddress((void**)&p_qkvT, g_qkvT);
    cudaGetSymbolAddress((void**)&p_projT, g_projT);
    cudaGetSymbolAddress((void**)&p_fc1T, g_fc1T);
    cudaGetSymbolAddress((void**)&p_fc2T, g_fc2T);

    cudaFuncSetAttribute(mma_gemm<0, 6>, cudaFuncAttributeMaxDynamicSharedMemorySize, GSMEM_6);
    cudaFuncSetAttribute(mma_gemm<1, 6>, cudaFuncAttributeMaxDynamicSharedMemorySize, GSMEM_6);
    cudaFuncSetAttribute(mma_gemm<2, 8>, cudaFuncAttributeMaxDynamicSharedMemorySize, GSMEM_8);
    cudaFuncSetAttribute(mma_gemm<3, 6>, cudaFuncAttributeMaxDynamicSharedMemorySize, GSMEM_6);

    // 0: LN1 + shift + window partition
    ln1_part_kernel<<<ROWS, 128>>>(x, n1g, n1b, p_win);
    // 1: transpose qkv weights
    transpose_k<<<dim3(QKVN / 32, CDIM / 32), dim3(32, 8)>>>(qkv_w, p_qkvT, CDIM, QKVN);
    // 2: QKV GEMM  (N=1152, BN=192 -> 6 col blocks)
    mma_gemm<0, 6><<<dim3(6, ROWS / 128), 256, GSMEM_6>>>(
        p_win, p_qkvT, qkv_b, p_qkv, CDIM, QKVN, nullptr);
    // 3: windowed attention
    attn_kernel<<<dim3(BN_WIN, NHEADS), 64>>>(p_qkv, rpb, attnmask, p_att);
    // 4: transpose proj weights
    transpose_k<<<dim3(CDIM / 32, CDIM / 32), dim3(32, 8)>>>(proj_w, p_projT, CDIM, CDIM);
    // 5: proj GEMM + window reverse + residual -> d_out  (N=384, BN=192 -> 2)
    mma_gemm<1, 6><<<dim3(2, ROWS / 128), 256, GSMEM_6>>>(
        p_att, p_projT, proj_b, out, CDIM, CDIM, x);
    // 6: LN2
    ln2_kernel<<<ROWS, 128>>>(out, n2g, n2b, p_win);
    // 7: transpose fc1 weights
    transpose_k<<<dim3(HID / 32, CDIM / 32), dim3(32, 8)>>>(fc1_w, p_fc1T, CDIM, HID);
    // 8: fc1 + GELU  (N=1536, BN=256 -> 6)
    mma_gemm<2, 8><<<dim3(6, ROWS / 128), 256, GSMEM_8>>>(
        p_win, p_fc1T, fc1_b, p_hid, CDIM, HID, nullptr);
    // 9: transpose fc2 weights
    transpose_k<<<dim3(CDIM / 32, HID / 32), dim3(32, 8)>>>(fc2_w, p_fc2T, HID, CDIM);
    // 10: fc2 + residual accumulate into d_out  (N=384, BN=192 -> 2, K=1536)
    mma_gemm<3, 6><<<dim3(2, ROWS / 128), 256, GSMEM_6>>>(
        p_hid, p_fc2T, fc2_b, out, HID, CDIM, nullptr);
}

// round 16
// speedup vs baseline: 1.1789x; 1.1789x over previous
#include <cuda_runtime.h>
#include <cuda_bf16.h>
#include <cstdint>
#include <math.h>

// ---------------- problem constants ----------------
#define BATCH 32
#define HH 56
#define WW 56
#define CDIM 384
#define NHEADS 12
#define HDIM 32
#define WSZ 7
#define NTOK 49
#define NWIN 64
#define BN_WIN 2048
#define ROWS 100352
#define HID 1536
#define QKVN 1152

// ---------------- scratch ----------------
__device__ float g_win[(size_t)ROWS * CDIM];
__device__ float g_qkv[(size_t)ROWS * QKVN];
__device__ float g_att[(size_t)ROWS * CDIM];
__device__ float g_hid[(size_t)ROWS * HID];
__device__ float g_qkvT[(size_t)QKVN * CDIM];
__device__ float g_projT[(size_t)CDIM * CDIM];
__device__ float g_fc1T[(size_t)HID * CDIM];
__device__ float g_fc2T[(size_t)CDIM * HID];

// ---------------- helpers ----------------
__device__ __forceinline__ uint32_t s2u(const void* p) {
    uint32_t a;
    asm("{ .reg .u64 t; cvta.to.shared.u64 t, %1; cvt.u32.u64 %0, t; }" : "=r"(a) : "l"(p));
    return a;
}
__device__ __forceinline__ void mma_tf32(float* c, const uint32_t* a, const uint32_t* b) {
    asm volatile(
        "mma.sync.aligned.m16n8k8.row.col.f32.tf32.tf32.f32 "
        "{%0,%1,%2,%3}, {%4,%5,%6,%7}, {%8,%9}, {%0,%1,%2,%3};"
        : "+f"(c[0]), "+f"(c[1]), "+f"(c[2]), "+f"(c[3])
        : "r"(a[0]), "r"(a[1]), "r"(a[2]), "r"(a[3]), "r"(b[0]), "r"(b[1]));
}
__device__ __forceinline__ void ldsm4(uint32_t* r, uint32_t addr) {
    asm volatile("ldmatrix.sync.aligned.m8n8.x4.shared.b16 {%0,%1,%2,%3}, [%4];"
                 : "=r"(r[0]), "=r"(r[1]), "=r"(r[2]), "=r"(r[3]) : "r"(addr));
}
__device__ __forceinline__ void cp16(uint32_t dst, const void* src) {
    asm volatile("cp.async.cg.shared.global [%0], [%1], 16;" :: "r"(dst), "l"(src));
}
#define CP_COMMIT() asm volatile("cp.async.commit_group;" ::: "memory")
#define CP_WAIT1()  asm volatile("cp.async.wait_group 1;" ::: "memory")

// packed f32x2 helpers (PTX sm_100+, not arch-'a' gated)
__device__ __forceinline__ unsigned long long pk2(float lo, float hi) {
    unsigned long long r;
    asm("mov.b64 %0, {%1, %2};" : "=l"(r) : "f"(lo), "f"(hi));
    return r;
}
__device__ __forceinline__ void upk2(float& lo, float& hi, unsigned long long v) {
    asm("mov.b64 {%0, %1}, %2;" : "=f"(lo), "=f"(hi) : "l"(v));
}
__device__ __forceinline__ void ffma2(unsigned long long& d, unsigned long long a,
                                      unsigned long long b) {
    asm("fma.rn.f32x2 %0, %1, %2, %0;" : "+l"(d) : "l"(a), "l"(b));
}

// Branchless erf-based GELU (A&S 7.1.26, abs err <= 1.5e-7)
__device__ __forceinline__ float fast_gelu(float x) {
    float u = x * 0.70710678118654752f;
    float a = fabsf(u);
    float t = __fdividef(1.0f, fmaf(0.3275911f, a, 1.0f));
    float p = fmaf(1.061405429f, t, -1.453152027f);
    p = fmaf(p, t, 1.421413741f);
    p = fmaf(p, t, -0.284496736f);
    p = fmaf(p, t, 0.254829592f);
    p = p * t;
    float e = __expf(-a * a);
    float er = fmaf(-p, e, 1.0f);
    er = copysignf(er, x);
    return 0.5f * x * (1.0f + er);
}

// ======================= tf32 mma.sync GEMM (R13 config) =======================
// Block 128x128, 8 warps (2m x 4n), warp tile 64x32, BK=32, 3-stage cp.async,
// ONE __syncthreads per K-chunk, wait_group 1.
#define STAGE_BYTES 32768
#define GSMEM_BYTES (3 * STAGE_BYTES)   // 96 KB -> 2 CTAs/SM

// EPI: 0 bias+store | 1 bias+scatter+residual | 2 bias+GELU | 3 bias+accumulate
template <int EPI>
__global__ void __launch_bounds__(256)
mma_gemm(const float* __restrict__ A, const float* __restrict__ Bt,
         const float* __restrict__ bias, float* __restrict__ C,
         int K, int Nm, const float* __restrict__ resid) {
    extern __shared__ __align__(1024) char smem[];
    const uint32_t sb = s2u(smem);

    const int tid = threadIdx.x;
    const int lane = tid & 31, wid = tid >> 5;
    const int wm = wid & 1, wn = wid >> 1;
    const int row0 = blockIdx.y * 128, col0 = blockIdx.x * 128;

    const float* Ab = A + (size_t)row0 * K;
    const float* Bb = Bt + (size_t)col0 * K;

    const int lr = tid >> 3;
    const int lc = tid & 7;

    const int x7 = lane & 7;
    const int rowA = wm * 64 + ((lane >> 3) & 1) * 8 + x7;
    const int cA = lane >> 4;
    const int rowB = wn * 32 + (lane >> 4) * 8 + x7;
    const int cB = (lane >> 3) & 1;

    float acc[4][4][4];
#pragma unroll
    for (int i = 0; i < 4; i++)
#pragma unroll
        for (int j = 0; j < 4; j++)
#pragma unroll
            for (int e = 0; e < 4; e++) acc[i][j][e] = 0.0f;

    const int nk = K >> 5;

    auto load_tile = [&](int s, int k0) {
        uint32_t As = sb + s * STAGE_BYTES;
        uint32_t Bs = As + 16384;
#pragma unroll
        for (int i = 0; i < 4; i++) {
            int r = lr + i * 32;
            uint32_t off = (uint32_t)r * 128 + ((uint32_t)(lc ^ (r & 7)) << 4);
            cp16(As + off, Ab + (size_t)r * K + k0 + lc * 4);
            cp16(Bs + off, Bb + (size_t)r * K + k0 + lc * 4);
        }
    };

    load_tile(0, 0); CP_COMMIT();
    load_tile(1, 32); CP_COMMIT();

    for (int it = 0; it < nk; ++it) {
        CP_WAIT1();
        __syncthreads();
        if (it + 2 < nk) load_tile((it + 2) % 3, (it + 2) << 5);
        CP_COMMIT();

        const uint32_t As = sb + (it % 3) * STAGE_BYTES;
        const uint32_t Bs = As + 16384;
#pragma unroll
        for (int kkp = 0; kkp < 4; kkp++) {
            uint32_t a[4][4], b[2][4];
#pragma unroll
            for (int mf = 0; mf < 4; mf++) {
                uint32_t addr = As + ((uint32_t)(rowA + mf * 16) << 7) +
                                ((uint32_t)((2 * kkp + cA) ^ x7) << 4);
                ldsm4(a[mf], addr);
            }
#pragma unroll
            for (int pr = 0; pr < 2; pr++) {
                uint32_t addr = Bs + ((uint32_t)(rowB + pr * 16) << 7) +
                                ((uint32_t)((2 * kkp + cB) ^ x7) << 4);
                ldsm4(b[pr], addr);
            }
#pragma unroll
            for (int mf = 0; mf < 4; mf++)
#pragma unroll
                for (int nf = 0; nf < 4; nf++)
                    mma_tf32(acc[mf][nf], a[mf], &b[nf >> 1][(nf & 1) * 2]);
        }
    }

    // ---------------- epilogue ----------------
#pragma unroll
    for (int mf = 0; mf < 4; mf++) {
#pragma unroll
        for (int h = 0; h < 2; h++) {
            int row = row0 + wm * 64 + mf * 16 + (lane >> 2) + h * 8;
            size_t base;
            if (EPI == 1) {
                int bn = row / NTOK, tok = row - bn * NTOK;
                int bbat = bn >> 6, w = bn & 63;
                int ii = (w >> 3) * WSZ + tok / WSZ;
                int jj = (w & 7) * WSZ + tok % WSZ;
                int hh = (ii < 53) ? ii + 3 : ii - 53;
                int ww2 = (jj < 53) ? jj + 3 : jj - 53;
                base = ((size_t)bbat * (HH * WW) + hh * WW + ww2) * CDIM;
            } else {
                base = (size_t)row * Nm;
            }
#pragma unroll
            for (int nf = 0; nf < 4; nf++) {
                int col = col0 + wn * 32 + nf * 8 + (lane & 3) * 2;
                float v0 = acc[mf][nf][h * 2 + 0] + bias[col];
                float v1 = acc[mf][nf][h * 2 + 1] + bias[col + 1];
                if (EPI == 2) {
                    v0 = fast_gelu(v0);
                    v1 = fast_gelu(v1);
                }
                size_t off = base + col;
                if (EPI == 1) {
                    float2 rr = *(const float2*)(resid + off);
                    float2 o; o.x = v0 + rr.x; o.y = v1 + rr.y;
                    *(float2*)(C + off) = o;
                } else if (EPI == 3) {
                    float2 o = *(float2*)(C + off);
                    o.x += v0; o.y += v1;
                    *(float2*)(C + off) = o;
                } else {
                    float2 o; o.x = v0; o.y = v1;
                    *(float2*)(C + off) = o;
                }
            }
        }
    }
}

// ---------------- weight transpose [K,N] -> [N,K] ----------------
__global__ void transpose_k(const float* __restrict__ W, float* __restrict__ Wt,
                            int K, int N) {
    __shared__ float t[32][33];
    int k0 = blockIdx.y * 32, n0 = blockIdx.x * 32;
    int x = threadIdx.x, y = threadIdx.y;
    for (int i = y; i < 32; i += 8) t[i][x] = W[(size_t)(k0 + i) * N + n0 + x];
    __syncthreads();
    for (int i = y; i < 32; i += 8) Wt[(size_t)(n0 + i) * K + k0 + x] = t[x][i];
}

// ---------------- LN1 + cyclic shift + window partition ----------------
__global__ void ln1_part_kernel(const float* __restrict__ x,
                                const float* __restrict__ g,
                                const float* __restrict__ b,
                                float* __restrict__ out) {
    int row = blockIdx.x;
    int tid = threadIdx.x;
    const float* xr = x + (size_t)row * CDIM;
    float v0 = xr[tid], v1 = xr[tid + 128], v2 = xr[tid + 256];
    float s = v0 + v1 + v2;
    float sq = v0 * v0 + v1 * v1 + v2 * v2;
#pragma unroll
    for (int o = 16; o; o >>= 1) {
        s += __shfl_down_sync(0xffffffffu, s, o);
        sq += __shfl_down_sync(0xffffffffu, sq, o);
    }
    __shared__ float rs[4], rq[4];
    int w = tid >> 5, l = tid & 31;
    if (l == 0) { rs[w] = s; rq[w] = sq; }
    __syncthreads();
    float ts = rs[0] + rs[1] + rs[2] + rs[3];
    float tq = rq[0] + rq[1] + rq[2] + rq[3];
    float mean = ts * (1.0f / CDIM);
    float var = tq * (1.0f / CDIM) - mean * mean;
    float rstd = rsqrtf(var + 1e-5f);

    int bb = row / (HH * WW);
    int rem = row - bb * (HH * WW);
    int hh = rem / WW, ww = rem - (rem / WW) * WW;
    int i = (hh >= 3) ? hh - 3 : hh + 53;
    int j = (ww >= 3) ? ww - 3 : ww + 53;
    int widx = (i / WSZ) * 8 + (j / WSZ);
    int tok = (i % WSZ) * WSZ + (j % WSZ);
    size_t drow = ((size_t)(bb * NWIN + widx) * NTOK + tok) * CDIM;
    out[drow + tid]       = (v0 - mean) * rstd * g[tid]       + b[tid];
    out[drow + tid + 128] = (v1 - mean) * rstd * g[tid + 128] + b[tid + 128];
    out[drow + tid + 256] = (v2 - mean) * rstd * g[tid + 256] + b[tid + 256];
}

// ---------------- LN2 ----------------
__global__ void ln2_kernel(const float* __restrict__ x,
                           const float* __restrict__ g,
                           const float* __restrict__ b,
                           float* __restrict__ out) {
    int row = blockIdx.x;
    int tid = threadIdx.x;
    const float* xr = x + (size_t)row * CDIM;
    float v0 = xr[tid], v1 = xr[tid + 128], v2 = xr[tid + 256];
    float s = v0 + v1 + v2;
    float sq = v0 * v0 + v1 * v1 + v2 * v2;
#pragma unroll
    for (int o = 16; o; o >>= 1) {
        s += __shfl_down_sync(0xffffffffu, s, o);
        sq += __shfl_down_sync(0xffffffffu, sq, o);
    }
    __shared__ float rs[4], rq[4];
    int w = tid >> 5, l = tid & 31;
    if (l == 0) { rs[w] = s; rq[w] = sq; }
    __syncthreads();
    float ts = rs[0] + rs[1] + rs[2] + rs[3];
    float tq = rq[0] + rq[1] + rq[2] + rq[3];
    float mean = ts * (1.0f / CDIM);
    float var = tq * (1.0f / CDIM) - mean * mean;
    float rstd = rsqrtf(var + 1e-5f);
    size_t o0 = (size_t)row * CDIM;
    out[o0 + tid]       = (v0 - mean) * rstd * g[tid]       + b[tid];
    out[o0 + tid + 128] = (v1 - mean) * rstd * g[tid + 128] + b[tid + 128];
    out[o0 + tid + 256] = (v2 - mean) * rstd * g[tid + 256] + b[tid + 256];
}

// ---------------- attention v2.1: row-per-thread, 4 QK accumulators ----------------
__global__ __launch_bounds__(64)
void attn_kernel(const float* __restrict__ qkv, const float* __restrict__ rpb,
                 const float* __restrict__ mask, float* __restrict__ out) {
    int bn = blockIdx.x;
    int h = blockIdx.y;
    int tid = threadIdx.x;

    __shared__ __align__(16) float ks[NTOK][HDIM];
    __shared__ __align__(16) float vs[NTOK][HDIM];

    const float* qbase = qkv + (size_t)bn * NTOK * QKVN + h * HDIM;
    for (int t = tid; t < NTOK * 8; t += 64) {
        int r = t >> 3, c = t & 7;
        const float4* src = (const float4*)(qbase + (size_t)r * QKVN);
        *(float4*)&ks[r][c * 4] = src[96 + c];
        *(float4*)&vs[r][c * 4] = src[192 + c];
    }

    bool valid = tid < NTOK;
    unsigned long long qp[16];
    if (valid) {
        const float4* qr = (const float4*)(qbase + (size_t)tid * QKVN);
#pragma unroll
        for (int c = 0; c < 8; c++) {
            float4 v = qr[c];
            float sc = 0.17677669529663687f;
            qp[2 * c + 0] = pk2(v.x * sc, v.y * sc);
            qp[2 * c + 1] = pk2(v.z * sc, v.w * sc);
        }
    }
    __syncthreads();

    float s[NTOK];
    if (valid) {
        const float* mrow = mask + (size_t)(bn & 63) * (NTOK * NTOK) + tid * NTOK;
        int yi = tid / WSZ, xi = tid - yi * WSZ;
#pragma unroll 7
        for (int j = 0; j < NTOK; j++) {
            int yj = j / WSZ, xj = j - yj * WSZ;
            float base = rpb[((yi - yj + 6) * 13 + (xi - xj + 6)) * NHEADS + h] + mrow[j];
            unsigned long long a0 = 0, a1 = 0, a2 = 0, a3 = 0;
            const ulonglong2* kr = (const ulonglong2*)&ks[j][0];
#pragma unroll
            for (int c = 0; c < 4; c++) {
                ulonglong2 k0 = kr[2 * c], k1 = kr[2 * c + 1];
                ffma2(a0, k0.x, qp[4 * c + 0]);
                ffma2(a1, k0.y, qp[4 * c + 1]);
                ffma2(a2, k1.x, qp[4 * c + 2]);
                ffma2(a3, k1.y, qp[4 * c + 3]);
            }
            float l0, h0, l1, h1, l2, h2, l3, h3;
            upk2(l0, h0, a0); upk2(l1, h1, a1);
            upk2(l2, h2, a2); upk2(l3, h3, a3);
            s[j] = base + ((l0 + h0) + (l1 + h1)) + ((l2 + h2) + (l3 + h3));
        }
        float m = -1e30f;
#pragma unroll
        for (int j = 0; j < NTOK; j++) m = fmaxf(m, s[j]);
        float sum = 0.0f;
#pragma unroll
        for (int j = 0; j < NTOK; j++) {
            float e = __expf(s[j] - m);
            s[j] = e;
            sum += e;
        }
        float inv = __fdividef(1.0f, sum);

        unsigned long long o[16];
#pragma unroll
        for (int k = 0; k < 16; k++) o[k] = 0;
#pragma unroll 7
        for (int j = 0; j < NTOK; j++) {
            float w = s[j] * inv;
            unsigned long long wp = pk2(w, w);
            const ulonglong2* vr = (const ulonglong2*)&vs[j][0];
#pragma unroll
            for (int c = 0; c < 8; c++) {
                ulonglong2 vv = vr[c];
                ffma2(o[2 * c + 0], vv.x, wp);
                ffma2(o[2 * c + 1], vv.y, wp);
            }
        }
        float ov[32];
#pragma unroll
        for (int k = 0; k < 16; k++) upk2(ov[2 * k], ov[2 * k + 1], o[k]);
        float* dst = out + ((size_t)bn * NTOK + tid) * CDIM + h * HDIM;
#pragma unroll
        for (int c = 0; c < 8; c++)
            *(float4*)(dst + c * 4) = make_float4(ov[4 * c], ov[4 * c + 1],
                                                  ov[4 * c + 2], ov[4 * c + 3]);
    }
}

// ---------------- launch ----------------
extern "C" void kernel_launch(void* const* d_in, const int* in_sizes, int n_in,
                              void* d_out, int out_size) {
    const float* x        = (const float*)d_in[0];
    const float* attnmask = (const float*)d_in[1];
    const float* n1g      = (const float*)d_in[2];
    const float* n1b      = (const float*)d_in[3];
    const float* qkv_w    = (const float*)d_in[4];
    const float* qkv_b    = (const float*)d_in[5];
    const float* rpb      = (const float*)d_in[6];
    const float* proj_w   = (const float*)d_in[7];
    const float* proj_b   = (const float*)d_in[8];
    const float* n2g      = (const float*)d_in[9];
    const float* n2b      = (const float*)d_in[10];
    const float* fc1_w    = (const float*)d_in[11];
    const float* fc1_b    = (const float*)d_in[12];
    const float* fc2_w    = (const float*)d_in[13];
    const float* fc2_b    = (const float*)d_in[14];
    float* out = (float*)d_out;

    float *p_win, *p_qkv, *p_att, *p_hid, *p_qkvT, *p_projT, *p_fc1T, *p_fc2T;
    cudaGetSymbolAddress((void**)&p_win, g_win);
    cudaGetSymbolAddress((void**)&p_qkv, g_qkv);
    cudaGetSymbolAddress((void**)&p_att, g_att);
    cudaGetSymbolAddress((void**)&p_hid, g_hid);
    cudaGetSymbolAddress((void**)&p_qkvT, g_qkvT);
    cudaGetSymbolAddress((void**)&p_projT, g_projT);
    cudaGetSymbolAddress((void**)&p_fc1T, g_fc1T);
    cudaGetSymbolAddress((void**)&p_fc2T, g_fc2T);

    cudaFuncSetAttribute(mma_gemm<0>, cudaFuncAttributeMaxDynamicSharedMemorySize, GSMEM_BYTES);
    cudaFuncSetAttribute(mma_gemm<1>, cudaFuncAttributeMaxDynamicSharedMemorySize, GSMEM_BYTES);
    cudaFuncSetAttribute(mma_gemm<2>, cudaFuncAttributeMaxDynamicSharedMemorySize, GSMEM_BYTES);
    cudaFuncSetAttribute(mma_gemm<3>, cudaFuncAttributeMaxDynamicSharedMemorySize, GSMEM_BYTES);

    // 0: LN1 + shift + window partition
    ln1_part_kernel<<<ROWS, 128>>>(x, n1g, n1b, p_win);
    // 1: transpose qkv weights
    transpose_k<<<dim3(QKVN / 32, CDIM / 32), dim3(32, 8)>>>(qkv_w, p_qkvT, CDIM, QKVN);
    // 2: QKV GEMM
    mma_gemm<0><<<dim3(QKVN / 128, ROWS / 128), 256, GSMEM_BYTES>>>(
        p_win, p_qkvT, qkv_b, p_qkv, CDIM, QKVN, nullptr);
    // 3: windowed attention
    attn_kernel<<<dim3(BN_WIN, NHEADS), 64>>>(p_qkv, rpb, attnmask, p_att);
    // 4: transpose proj weights
    transpose_k<<<dim3(CDIM / 32, CDIM / 32), dim3(32, 8)>>>(proj_w, p_projT, CDIM, CDIM);
    // 5: proj GEMM + window reverse + residual -> d_out
    mma_gemm<1><<<dim3(CDIM / 128, ROWS / 128), 256, GSMEM_BYTES>>>(
        p_att, p_projT, proj_b, out, CDIM, CDIM, x);
    // 6: LN2
    ln2_kernel<<<ROWS, 128>>>(out, n2g, n2b, p_win);
    // 7: transpose fc1 weights
    transpose_k<<<dim3(HID / 32, CDIM / 32), dim3(32, 8)>>>(fc1_w, p_fc1T, CDIM, HID);
    // 8: fc1 + GELU
    mma_gemm<2><<<dim3(HID / 128, ROWS / 128), 256, GSMEM_BYTES>>>(
        p_win, p_fc1T, fc1_b, p_hid, CDIM, HID, nullptr);
    // 9: transpose fc2 weights
    transpose_k<<<dim3(CDIM / 32, HID / 32), dim3(32, 8)>>>(fc2_w, p_fc2T, HID, CDIM);
    // 10: fc2 + residual accumulate into d_out
    mma_gemm<3><<<dim3(CDIM / 128, ROWS / 128), 256, GSMEM_BYTES>>>(
        p_hid, p_fc2T, fc2_b, out, HID, CDIM, nullptr);
}